// round 10
// baseline (speedup 1.0000x reference)
#include <cuda_runtime.h>
#include <cuda_fp16.h>
#include <math.h>
#include <stdint.h>

#define BATCH  4
#define SEQ    1500
#define NSTATE 1024
#define NQKV   3072
#define NHEAD  16
#define HDIM   64
#define TOK    (BATCH*SEQ)   // 6000
#define NW     (NSTATE*NSTATE)
#define NX     (TOK*NSTATE)

// Scratch (allocation-free rule: __device__ globals), all fp16
__device__ __half g_x[NX];
__device__ __half g_qkv[TOK*NQKV];          // fused q|k|v, row stride 3072
__device__ __half g_att[NX];
__device__ __half g_wqkv[NQKV*NSTATE];
__device__ __half g_wo[NW];
__device__ float  g_bqkv[NQKV];

// ===========================================================================
// helpers
// ===========================================================================
__device__ __forceinline__ uint32_t s2u(const void* p) {
    uint32_t a;
    asm("{ .reg .u64 t; cvta.to.shared.u64 t, %1; cvt.u32.u64 %0, t; }"
        : "=r"(a) : "l"(p));
    return a;
}

__device__ __forceinline__ void ldsm4(uint32_t& r0, uint32_t& r1,
                                      uint32_t& r2, uint32_t& r3, uint32_t addr) {
    asm volatile("ldmatrix.sync.aligned.m8n8.x4.shared.b16 {%0,%1,%2,%3}, [%4];"
        : "=r"(r0), "=r"(r1), "=r"(r2), "=r"(r3) : "r"(addr));
}
__device__ __forceinline__ void ldsm4t(uint32_t& r0, uint32_t& r1,
                                       uint32_t& r2, uint32_t& r3, uint32_t addr) {
    asm volatile("ldmatrix.sync.aligned.m8n8.x4.trans.shared.b16 {%0,%1,%2,%3}, [%4];"
        : "=r"(r0), "=r"(r1), "=r"(r2), "=r"(r3) : "r"(addr));
}

__device__ __forceinline__ void mma16(float* c, uint32_t a0, uint32_t a1,
                                      uint32_t a2, uint32_t a3,
                                      uint32_t b0, uint32_t b1) {
    asm volatile("mma.sync.aligned.m16n8k16.row.col.f32.f16.f16.f32 "
        "{%0,%1,%2,%3}, {%4,%5,%6,%7}, {%8,%9}, {%0,%1,%2,%3};"
        : "+f"(c[0]), "+f"(c[1]), "+f"(c[2]), "+f"(c[3])
        : "r"(a0), "r"(a1), "r"(a2), "r"(a3), "r"(b0), "r"(b1));
}

__device__ __forceinline__ uint32_t packh2(float a, float b) {
    __half2 h = __floats2half2_rn(a, b);
    return *(uint32_t*)&h;
}

#define CP16(dst, src) \
    asm volatile("cp.async.cg.shared.global [%0], [%1], 16;" :: "r"(dst), "l"(src))
#define CP16P(dst, src, sz) \
    asm volatile("cp.async.cg.shared.global [%0], [%1], 16, %2;" :: "r"(dst), "l"(src), "r"(sz))
#define CP_COMMIT() asm volatile("cp.async.commit_group;" ::: "memory")
#define CP_WAIT(n)  asm volatile("cp.async.wait_group %0;" :: "n"(n) : "memory")

// ===========================================================================
// single fused prepass
// ===========================================================================
#define PREP_CHUNKS ((NX + 4*NW + NQKV) / 8)

__global__ void prep_kernel(const float* __restrict__ x,
                            const float* __restrict__ Wq,
                            const float* __restrict__ Wk,
                            const float* __restrict__ Wv,
                            const float* __restrict__ Wo,
                            const float* __restrict__ bq,
                            const float* __restrict__ bv)
{
    int i = (blockIdx.x * blockDim.x + threadIdx.x) * 8;
    const float* src;
    __half* dst;
    if (i < NX) {
        src = x + i; dst = g_x + i;
    } else if (i < NX + 3*NW) {
        int j = i - NX;
        src = (j < NW) ? Wq + j : (j < 2*NW) ? Wk + (j - NW) : Wv + (j - 2*NW);
        dst = g_wqkv + j;
    } else if (i < NX + 4*NW) {
        int j = i - NX - 3*NW;
        src = Wo + j; dst = g_wo + j;
    } else if (i < NX + 4*NW + NQKV) {
        int j = i - NX - 4*NW;
        #pragma unroll
        for (int e = 0; e < 8; e++) {
            int c = j + e;
            float v = 0.f;
            if (c < 1024)       v = bq[c];
            else if (c >= 2048) v = bv[c - 2048];
            g_bqkv[c] = v;
        }
        return;
    } else return;

    float4 v0 = *(const float4*)(src);
    float4 v1 = *(const float4*)(src + 4);
    __half2 h[4];
    h[0] = __floats2half2_rn(v0.x, v0.y);
    h[1] = __floats2half2_rn(v0.z, v0.w);
    h[2] = __floats2half2_rn(v1.x, v1.y);
    h[3] = __floats2half2_rn(v1.z, v1.w);
    *(uint4*)dst = *(uint4*)h;
}

// ===========================================================================
// GEMM: C = A @ W^T + bias. Block 128x128, BK=64 halves, 256 thr = 8 warps
// (2m x 4n), warp tile 64x32. SMEM rows 144B, conflict-free LDSM.
// 3-stage cp.async ring, ONE __syncthreads per K-stage.
// ===========================================================================
#define G_STAGE_B (256*144)             // 36864 bytes
#define GEMM_SMEM (3*G_STAGE_B)         // 110592 -> 2 CTA/SM

template<bool HALF_OUT>
__global__ __launch_bounds__(256, 2) void gemm_tc(
    const __half* __restrict__ A, const __half* __restrict__ W,
    const float* __restrict__ bias, void* __restrict__ Cv, int M, int N)
{
    extern __shared__ __align__(16) char smraw[];
    const uint32_t sb = s2u(smraw);
    const int tid = threadIdx.x;
    const int wid = tid >> 5, lane = tid & 31;
    const int wm = wid >> 2, wn = wid & 3;
    const int g = lane >> 2, q = lane & 3;
    const int m0 = blockIdx.y * 128;
    const int n0 = blockIdx.x * 128;

    const uint32_t lmRow = (uint32_t)(lane & 15) * 144 + (uint32_t)(lane >> 4) * 16;
    uint32_t aBase[4], bBase[2];
    #pragma unroll
    for (int mi = 0; mi < 4; mi++)
        aBase[mi] = (uint32_t)(64*wm + 16*mi) * 144 + lmRow;
    #pragma unroll
    for (int p = 0; p < 2; p++)
        bBase[p] = 128u*144 + (uint32_t)(32*wn + 16*p) * 144 + lmRow;

    float c[4][4][4];
    #pragma unroll
    for (int mi = 0; mi < 4; mi++)
        #pragma unroll
        for (int ni = 0; ni < 4; ni++)
            #pragma unroll
            for (int e = 0; e < 4; e++) c[mi][ni][e] = 0.f;

    auto load_stage = [&](int s) {
        const uint32_t base = sb + (s % 3) * G_STAGE_B;
        const int k0 = s * 64;
        #pragma unroll
        for (int i = 0; i < 4; i++) {
            int idx = tid + 256*i;
            int row = idx >> 3, lc = idx & 7;
            int gm = m0 + row;
            const __half* asrc = A + (size_t)(gm < M ? gm : 0) * NSTATE + k0 + lc*8;
            CP16P(base + row*144 + lc*16, asrc, (gm < M) ? 16 : 0);
            const __half* bsrc = W + (size_t)(n0 + row) * NSTATE + k0 + lc*8;
            CP16(base + 128*144 + row*144 + lc*16, bsrc);
        }
    };

    load_stage(0); CP_COMMIT();
    load_stage(1); CP_COMMIT();

    for (int s = 0; s < 16; s++) {
        CP_WAIT(1);
        __syncthreads();

        const uint32_t stg = sb + (s % 3) * G_STAGE_B;
        #pragma unroll
        for (int kd = 0; kd < 4; kd++) {
            uint32_t a[4][4];
            #pragma unroll
            for (int mi = 0; mi < 4; mi++)
                ldsm4(a[mi][0], a[mi][1], a[mi][2], a[mi][3],
                      stg + aBase[mi] + kd*32);
            #pragma unroll
            for (int p = 0; p < 2; p++) {
                uint32_t t0, t1, t2, t3;
                ldsm4(t0, t1, t2, t3, stg + bBase[p] + kd*32);
                #pragma unroll
                for (int mi = 0; mi < 4; mi++) {
                    mma16(c[mi][2*p],   a[mi][0], a[mi][1], a[mi][2], a[mi][3], t0, t2);
                    mma16(c[mi][2*p+1], a[mi][0], a[mi][1], a[mi][2], a[mi][3], t1, t3);
                }
            }
        }

        if (s + 2 < 16) load_stage(s + 2);
        CP_COMMIT();
    }

    #pragma unroll
    for (int ni = 0; ni < 4; ni++) {
        const int col = n0 + 32*wn + 8*ni + 2*q;
        float bx = 0.f, by = 0.f;
        if (bias) { bx = bias[col]; by = bias[col+1]; }
        #pragma unroll
        for (int mi = 0; mi < 4; mi++) {
            int row_lo = m0 + 64*wm + 16*mi + g;
            float v0 = c[mi][ni][0] + bx, v1 = c[mi][ni][1] + by;
            float v2 = c[mi][ni][2] + bx, v3 = c[mi][ni][3] + by;
            if (HALF_OUT) {
                __half* C = (__half*)Cv;
                if (row_lo < M)
                    *(__half2*)(C + (size_t)row_lo*N + col) = __floats2half2_rn(v0, v1);
                if (row_lo + 8 < M)
                    *(__half2*)(C + (size_t)(row_lo+8)*N + col) = __floats2half2_rn(v2, v3);
            } else {
                float* C = (float*)Cv;
                if (row_lo < M)
                    *(float2*)(C + (size_t)row_lo*N + col) = make_float2(v0, v1);
                if (row_lo + 8 < M)
                    *(float2*)(C + (size_t)(row_lo+8)*N + col) = make_float2(v2, v3);
            }
        }
    }
}

// ===========================================================================
// Flash attention, fp16 mma.sync. 128 threads = 4 warps, warp tile 32x64.
// 3-buffer KV ring, ONE __syncthreads per kv-iter, register-resident P.
// NEW: __launch_bounds__(128,3) -> 3 CTA/SM (12 warps), regs capped at 170.
// SMEM: Q[128] + (K|V)[64] x3 rings, rows 144B = 73728 B; x3 CTAs = 216 KB.
// ===========================================================================
#define KV0H  9216
#define KVSTG 9216
#define ATT_SMEM ((KV0H + 3*KVSTG) * 2)   // 73728 bytes

__global__ __launch_bounds__(128, 3) void attn_tc(
    const __half* __restrict__ QKV, __half* __restrict__ Og)
{
    extern __shared__ __align__(16) char smraw[];
    const uint32_t sb = s2u(smraw);
    const int tid  = threadIdx.x;
    const int w    = tid >> 5, lane = tid & 31;
    const int g    = lane >> 2, q = lane & 3;
    const int q0   = blockIdx.x * 128;
    const int h    = blockIdx.y;
    const int b    = blockIdx.z;

    const __half* Qg = QKV;
    const __half* Kg = QKV + 1024;
    const __half* Vg = QKV + 2048;

    const uint32_t lmRow = (uint32_t)(lane & 15) * 144 + (uint32_t)(lane >> 4) * 16;
    uint32_t qA[2];
    qA[0] = sb + (uint32_t)(32*w)*144 + lmRow;
    qA[1] = sb + (uint32_t)(32*w + 16)*144 + lmRow;

    // load Q tile: 128 rows x 8 chunks = 1024 chunks, 8/thread  (group 0)
    {
        #pragma unroll
        for (int i = 0; i < 8; i++) {
            int idx = tid + 128*i;
            int row = idx >> 3, lc = idx & 7;
            int s = q0 + row;
            const __half* src = Qg + (size_t)(b*SEQ + (s < SEQ ? s : 0))*NQKV
                                + h*HDIM + lc*8;
            CP16P(sb + row*144 + lc*16, src, (s < SEQ) ? 16 : 0);
        }
        CP_COMMIT();
    }

    const int NKT = (SEQ + 63) / 64;   // 24
    auto load_kv = [&](int kt) {
        const uint32_t Kb = sb + (KV0H + (kt % 3)*KVSTG)*2;
        const uint32_t Vb = Kb + 4608*2;
        #pragma unroll
        for (int i = 0; i < 4; i++) {
            int idx = tid + 128*i;
            int row = idx >> 3, lc = idx & 7;
            int s = kt*64 + row;
            size_t base = (size_t)(b*SEQ + (s < SEQ ? s : 0))*NQKV + h*HDIM + lc*8;
            int ok = (s < SEQ) ? 16 : 0;
            CP16P(Kb + row*144 + lc*16, Kg + base, ok);
            CP16P(Vb + row*144 + lc*16, Vg + base, ok);
        }
    };

    load_kv(0); CP_COMMIT();
    load_kv(1); CP_COMMIT();

    float o[2][8][4];
    float m_lo[2], m_hi[2], l_lo[2], l_hi[2];
    #pragma unroll
    for (int mi = 0; mi < 2; mi++) {
        m_lo[mi] = -1e30f; m_hi[mi] = -1e30f; l_lo[mi] = 0.f; l_hi[mi] = 0.f;
        #pragma unroll
        for (int nt = 0; nt < 8; nt++)
            #pragma unroll
            for (int e = 0; e < 4; e++) o[mi][nt][e] = 0.f;
    }

    for (int kt = 0; kt < NKT; kt++) {
        CP_WAIT(1);
        __syncthreads();

        const uint32_t Kb = sb + (KV0H + (kt % 3)*KVSTG)*2;
        const uint32_t Vb = Kb + 4608*2;

        // ---- S = Q K^T (two m-subtiles share each K fragment) ----
        float s[2][8][4];
        #pragma unroll
        for (int mi = 0; mi < 2; mi++)
            #pragma unroll
            for (int nt = 0; nt < 8; nt++)
                #pragma unroll
                for (int e = 0; e < 4; e++) s[mi][nt][e] = 0.f;

        #pragma unroll
        for (int kd = 0; kd < 4; kd++) {
            uint32_t a[2][4];
            #pragma unroll
            for (int mi = 0; mi < 2; mi++)
                ldsm4(a[mi][0], a[mi][1], a[mi][2], a[mi][3], qA[mi] + kd*32);
            #pragma unroll
            for (int p = 0; p < 4; p++) {
                uint32_t t0, t1, t2, t3;
                ldsm4(t0, t1, t2, t3, Kb + (uint32_t)(16*p)*144 + lmRow + kd*32);
                #pragma unroll
                for (int mi = 0; mi < 2; mi++) {
                    mma16(s[mi][2*p],   a[mi][0], a[mi][1], a[mi][2], a[mi][3], t0, t2);
                    mma16(s[mi][2*p+1], a[mi][0], a[mi][1], a[mi][2], a[mi][3], t1, t3);
                }
            }
        }

        // ---- online softmax per m-subtile ----
        const int jb = kt*64 + 2*q;
        #pragma unroll
        for (int mi = 0; mi < 2; mi++) {
            float mxlo = -1e30f, mxhi = -1e30f;
            #pragma unroll
            for (int nt = 0; nt < 8; nt++) {
                const int j0 = jb + 8*nt;
                s[mi][nt][0] = (j0     < SEQ) ? s[mi][nt][0]*0.125f : -1e30f;
                s[mi][nt][1] = (j0 + 1 < SEQ) ? s[mi][nt][1]*0.125f : -1e30f;
                s[mi][nt][2] = (j0     < SEQ) ? s[mi][nt][2]*0.125f : -1e30f;
                s[mi][nt][3] = (j0 + 1 < SEQ) ? s[mi][nt][3]*0.125f : -1e30f;
                mxlo = fmaxf(mxlo, fmaxf(s[mi][nt][0], s[mi][nt][1]));
                mxhi = fmaxf(mxhi, fmaxf(s[mi][nt][2], s[mi][nt][3]));
            }
            mxlo = fmaxf(mxlo, __shfl_xor_sync(0xffffffffu, mxlo, 1));
            mxlo = fmaxf(mxlo, __shfl_xor_sync(0xffffffffu, mxlo, 2));
            mxhi = fmaxf(mxhi, __shfl_xor_sync(0xffffffffu, mxhi, 1));
            mxhi = fmaxf(mxhi, __shfl_xor_sync(0xffffffffu, mxhi, 2));

            const float mn_lo = fmaxf(m_lo[mi], mxlo);
            const float mn_hi = fmaxf(m_hi[mi], mxhi);
            const float al_lo = __expf(m_lo[mi] - mn_lo);
            const float al_hi = __expf(m_hi[mi] - mn_hi);
            float sl = 0.f, sh = 0.f;
            #pragma unroll
            for (int nt = 0; nt < 8; nt++) {
                s[mi][nt][0] = __expf(s[mi][nt][0] - mn_lo);
                s[mi][nt][1] = __expf(s[mi][nt][1] - mn_lo);
                s[mi][nt][2] = __expf(s[mi][nt][2] - mn_hi);
                s[mi][nt][3] = __expf(s[mi][nt][3] - mn_hi);
                sl += s[mi][nt][0] + s[mi][nt][1];
                sh += s[mi][nt][2] + s[mi][nt][3];
            }
            sl += __shfl_xor_sync(0xffffffffu, sl, 1);
            sl += __shfl_xor_sync(0xffffffffu, sl, 2);
            sh += __shfl_xor_sync(0xffffffffu, sh, 1);
            sh += __shfl_xor_sync(0xffffffffu, sh, 2);
            l_lo[mi] = l_lo[mi] * al_lo + sl;  m_lo[mi] = mn_lo;
            l_hi[mi] = l_hi[mi] * al_hi + sh;  m_hi[mi] = mn_hi;
            #pragma unroll
            for (int nt = 0; nt < 8; nt++) {
                o[mi][nt][0] *= al_lo; o[mi][nt][1] *= al_lo;
                o[mi][nt][2] *= al_hi; o[mi][nt][3] *= al_hi;
            }
        }

        // ---- O += P V : V fragments loaded once, used by both m-subtiles ----
        #pragma unroll
        for (int kj = 0; kj < 4; kj++) {
            uint32_t a[2][4];
            #pragma unroll
            for (int mi = 0; mi < 2; mi++) {
                a[mi][0] = packh2(s[mi][2*kj][0],   s[mi][2*kj][1]);
                a[mi][1] = packh2(s[mi][2*kj][2],   s[mi][2*kj][3]);
                a[mi][2] = packh2(s[mi][2*kj+1][0], s[mi][2*kj+1][1]);
                a[mi][3] = packh2(s[mi][2*kj+1][2], s[mi][2*kj+1][3]);
            }
            const uint32_t vrow = Vb + (uint32_t)(16*kj)*144 + lmRow;
            #pragma unroll
            for (int dt = 0; dt < 4; dt++) {
                uint32_t t0, t1, t2, t3;
                ldsm4t(t0, t1, t2, t3, vrow + dt*32);
                #pragma unroll
                for (int mi = 0; mi < 2; mi++) {
                    mma16(o[mi][2*dt],   a[mi][0], a[mi][1], a[mi][2], a[mi][3], t0, t1);
                    mma16(o[mi][2*dt+1], a[mi][0], a[mi][1], a[mi][2], a[mi][3], t2, t3);
                }
            }
        }

        // prefetch kv(kt+2) into the ring slot freed this iteration
        if (kt + 2 < NKT) load_kv(kt + 2);
        CP_COMMIT();
    }

    // ---- epilogue ----
    #pragma unroll
    for (int mi = 0; mi < 2; mi++) {
        const float il_lo = 1.f / l_lo[mi], il_hi = 1.f / l_hi[mi];
        const int row_lo = q0 + 32*w + 16*mi + g;
        const int row_hi = row_lo + 8;
        #pragma unroll
        for (int nt = 0; nt < 8; nt++) {
            const int d = 8*nt + 2*q;
            if (row_lo < SEQ)
                *(__half2*)(Og + (size_t)(b*SEQ + row_lo)*NSTATE + h*HDIM + d) =
                    __floats2half2_rn(o[mi][nt][0]*il_lo, o[mi][nt][1]*il_lo);
            if (row_hi < SEQ)
                *(__half2*)(Og + (size_t)(b*SEQ + row_hi)*NSTATE + h*HDIM + d) =
                    __floats2half2_rn(o[mi][nt][2]*il_hi, o[mi][nt][3]*il_hi);
        }
    }
}

// ===========================================================================
extern "C" void kernel_launch(void* const* d_in, const int* in_sizes, int n_in,
                              void* d_out, int out_size)
{
    const float* x  = (const float*)d_in[0];
    const float* Wq = (const float*)d_in[1];
    const float* bq = (const float*)d_in[2];
    const float* Wk = (const float*)d_in[3];
    const float* Wv = (const float*)d_in[4];
    const float* bv = (const float*)d_in[5];
    const float* Wo = (const float*)d_in[6];
    const float* bo = (const float*)d_in[7];
    float* out = (float*)d_out;

    __half *xh, *wqkv, *wo, *qkv, *att;
    float* bqkv;
    cudaGetSymbolAddress((void**)&xh,   g_x);
    cudaGetSymbolAddress((void**)&wqkv, g_wqkv);
    cudaGetSymbolAddress((void**)&wo,   g_wo);
    cudaGetSymbolAddress((void**)&qkv,  g_qkv);
    cudaGetSymbolAddress((void**)&att,  g_att);
    cudaGetSymbolAddress((void**)&bqkv, g_bqkv);

    cudaFuncSetAttribute(gemm_tc<true>,
                         cudaFuncAttributeMaxDynamicSharedMemorySize, GEMM_SMEM);
    cudaFuncSetAttribute(gemm_tc<false>,
                         cudaFuncAttributeMaxDynamicSharedMemorySize, GEMM_SMEM);
    cudaFuncSetAttribute(attn_tc,
                         cudaFuncAttributeMaxDynamicSharedMemorySize, ATT_SMEM);

    prep_kernel<<<(PREP_CHUNKS + 255)/256, 256>>>(x, Wq, Wk, Wv, Wo, bq, bv);

    // fused QKV projection: [6000,1024] @ [3072,1024]^T -> [6000,3072]
    gemm_tc<true><<<dim3(NQKV/128, (TOK+127)/128), 256, GEMM_SMEM>>>(
        xh, wqkv, bqkv, qkv, TOK, NQKV);

    attn_tc<<<dim3((SEQ+127)/128, NHEAD, BATCH), 128, ATT_SMEM>>>(qkv, att);

    gemm_tc<false><<<dim3(NSTATE/128, (TOK+127)/128), 256, GEMM_SMEM>>>(
        att, wo, bo, out, TOK, NSTATE);
}

// round 11
// speedup vs baseline: 1.0190x; 1.0190x over previous
#include <cuda_runtime.h>
#include <cuda_fp16.h>
#include <math.h>
#include <stdint.h>

#define BATCH  4
#define SEQ    1500
#define NSTATE 1024
#define NQKV   3072
#define NHEAD  16
#define HDIM   64
#define TOK    (BATCH*SEQ)   // 6000
#define NW     (NSTATE*NSTATE)
#define NX     (TOK*NSTATE)

// Scratch (allocation-free rule: __device__ globals), all fp16
__device__ __half g_x[NX];
__device__ __half g_qkv[TOK*NQKV];          // fused q|k|v, row stride 3072
__device__ __half g_att[NX];
__device__ __half g_wqkv[NQKV*NSTATE];
__device__ __half g_wo[NW];
__device__ float  g_bqkv[NQKV];

// ===========================================================================
// helpers
// ===========================================================================
__device__ __forceinline__ uint32_t s2u(const void* p) {
    uint32_t a;
    asm("{ .reg .u64 t; cvta.to.shared.u64 t, %1; cvt.u32.u64 %0, t; }"
        : "=r"(a) : "l"(p));
    return a;
}

__device__ __forceinline__ void ldsm4(uint32_t& r0, uint32_t& r1,
                                      uint32_t& r2, uint32_t& r3, uint32_t addr) {
    asm volatile("ldmatrix.sync.aligned.m8n8.x4.shared.b16 {%0,%1,%2,%3}, [%4];"
        : "=r"(r0), "=r"(r1), "=r"(r2), "=r"(r3) : "r"(addr));
}
__device__ __forceinline__ void ldsm4t(uint32_t& r0, uint32_t& r1,
                                       uint32_t& r2, uint32_t& r3, uint32_t addr) {
    asm volatile("ldmatrix.sync.aligned.m8n8.x4.trans.shared.b16 {%0,%1,%2,%3}, [%4];"
        : "=r"(r0), "=r"(r1), "=r"(r2), "=r"(r3) : "r"(addr));
}

__device__ __forceinline__ void mma16(float* c, uint32_t a0, uint32_t a1,
                                      uint32_t a2, uint32_t a3,
                                      uint32_t b0, uint32_t b1) {
    asm volatile("mma.sync.aligned.m16n8k16.row.col.f32.f16.f16.f32 "
        "{%0,%1,%2,%3}, {%4,%5,%6,%7}, {%8,%9}, {%0,%1,%2,%3};"
        : "+f"(c[0]), "+f"(c[1]), "+f"(c[2]), "+f"(c[3])
        : "r"(a0), "r"(a1), "r"(a2), "r"(a3), "r"(b0), "r"(b1));
}

__device__ __forceinline__ uint32_t packh2(float a, float b) {
    __half2 h = __floats2half2_rn(a, b);
    return *(uint32_t*)&h;
}

#define CP16(dst, src) \
    asm volatile("cp.async.cg.shared.global [%0], [%1], 16;" :: "r"(dst), "l"(src))
#define CP16P(dst, src, sz) \
    asm volatile("cp.async.cg.shared.global [%0], [%1], 16, %2;" :: "r"(dst), "l"(src), "r"(sz))
#define CP_COMMIT() asm volatile("cp.async.commit_group;" ::: "memory")
#define CP_WAIT(n)  asm volatile("cp.async.wait_group %0;" :: "n"(n) : "memory")

// ===========================================================================
// single fused prepass
// ===========================================================================
#define PREP_CHUNKS ((NX + 4*NW + NQKV) / 8)

__global__ void prep_kernel(const float* __restrict__ x,
                            const float* __restrict__ Wq,
                            const float* __restrict__ Wk,
                            const float* __restrict__ Wv,
                            const float* __restrict__ Wo,
                            const float* __restrict__ bq,
                            const float* __restrict__ bv)
{
    int i = (blockIdx.x * blockDim.x + threadIdx.x) * 8;
    const float* src;
    __half* dst;
    if (i < NX) {
        src = x + i; dst = g_x + i;
    } else if (i < NX + 3*NW) {
        int j = i - NX;
        src = (j < NW) ? Wq + j : (j < 2*NW) ? Wk + (j - NW) : Wv + (j - 2*NW);
        dst = g_wqkv + j;
    } else if (i < NX + 4*NW) {
        int j = i - NX - 3*NW;
        src = Wo + j; dst = g_wo + j;
    } else if (i < NX + 4*NW + NQKV) {
        int j = i - NX - 4*NW;
        #pragma unroll
        for (int e = 0; e < 8; e++) {
            int c = j + e;
            float v = 0.f;
            if (c < 1024)       v = bq[c];
            else if (c >= 2048) v = bv[c - 2048];
            g_bqkv[c] = v;
        }
        return;
    } else return;

    float4 v0 = *(const float4*)(src);
    float4 v1 = *(const float4*)(src + 4);
    __half2 h[4];
    h[0] = __floats2half2_rn(v0.x, v0.y);
    h[1] = __floats2half2_rn(v0.z, v0.w);
    h[2] = __floats2half2_rn(v1.x, v1.y);
    h[3] = __floats2half2_rn(v1.z, v1.w);
    *(uint4*)dst = *(uint4*)h;
}

// ===========================================================================
// GEMM: C = A @ W^T + bias. Templated on MI (m-fragments per warp):
//   block tile = (MI*32) x 128, 256 thr = 8 warps (2m x 4n),
//   warp tile = (MI*16) x 32. BK=64 halves, SMEM rows 144B (LDSM clean).
// 3-stage cp.async ring, ONE __syncthreads per K-stage.
// MI=4: 128x128 (best crossbar ratio, QKV GEMM).
// MI=2: 64x128  (finer grid, kills out-GEMM wave quantization).
// ===========================================================================
template<int MI, bool HALF_OUT>
__global__ __launch_bounds__(256, 2) void gemm_tc(
    const __half* __restrict__ A, const __half* __restrict__ W,
    const float* __restrict__ bias, void* __restrict__ Cv, int M, int N)
{
    constexpr int AROWS   = MI * 32;
    constexpr int SROWS   = AROWS + 128;
    constexpr int STAGE_B = SROWS * 144;

    extern __shared__ __align__(16) char smraw[];
    const uint32_t sb = s2u(smraw);
    const int tid = threadIdx.x;
    const int wid = tid >> 5, lane = tid & 31;
    const int wm = wid >> 2, wn = wid & 3;
    const int g = lane >> 2, q = lane & 3;
    const int m0 = blockIdx.y * AROWS;
    const int n0 = blockIdx.x * 128;

    const uint32_t lmRow = (uint32_t)(lane & 15) * 144 + (uint32_t)(lane >> 4) * 16;
    uint32_t aBase[MI], bBase[2];
    #pragma unroll
    for (int mi = 0; mi < MI; mi++)
        aBase[mi] = (uint32_t)(MI*16*wm + 16*mi) * 144 + lmRow;
    #pragma unroll
    for (int p = 0; p < 2; p++)
        bBase[p] = (uint32_t)AROWS*144 + (uint32_t)(32*wn + 16*p) * 144 + lmRow;

    float c[MI][4][4];
    #pragma unroll
    for (int mi = 0; mi < MI; mi++)
        #pragma unroll
        for (int ni = 0; ni < 4; ni++)
            #pragma unroll
            for (int e = 0; e < 4; e++) c[mi][ni][e] = 0.f;

    auto load_stage = [&](int s) {
        const uint32_t base = sb + (s % 3) * STAGE_B;
        const int k0 = s * 64;
        #pragma unroll
        for (int i = 0; i < (SROWS*8)/256; i++) {
            int idx = tid + 256*i;
            int row = idx >> 3, lc = idx & 7;
            if (row < AROWS) {
                int gm = m0 + row;
                const __half* asrc = A + (size_t)(gm < M ? gm : 0) * NSTATE + k0 + lc*8;
                CP16P(base + row*144 + lc*16, asrc, (gm < M) ? 16 : 0);
            } else {
                const __half* bsrc = W + (size_t)(n0 + row - AROWS) * NSTATE + k0 + lc*8;
                CP16(base + row*144 + lc*16, bsrc);
            }
        }
    };

    load_stage(0); CP_COMMIT();
    load_stage(1); CP_COMMIT();

    for (int s = 0; s < 16; s++) {
        CP_WAIT(1);
        __syncthreads();

        const uint32_t stg = sb + (s % 3) * STAGE_B;
        #pragma unroll
        for (int kd = 0; kd < 4; kd++) {
            uint32_t a[MI][4];
            #pragma unroll
            for (int mi = 0; mi < MI; mi++)
                ldsm4(a[mi][0], a[mi][1], a[mi][2], a[mi][3],
                      stg + aBase[mi] + kd*32);
            #pragma unroll
            for (int p = 0; p < 2; p++) {
                uint32_t t0, t1, t2, t3;
                ldsm4(t0, t1, t2, t3, stg + bBase[p] + kd*32);
                #pragma unroll
                for (int mi = 0; mi < MI; mi++) {
                    mma16(c[mi][2*p],   a[mi][0], a[mi][1], a[mi][2], a[mi][3], t0, t2);
                    mma16(c[mi][2*p+1], a[mi][0], a[mi][1], a[mi][2], a[mi][3], t1, t3);
                }
            }
        }

        if (s + 2 < 16) load_stage(s + 2);
        CP_COMMIT();
    }

    #pragma unroll
    for (int ni = 0; ni < 4; ni++) {
        const int col = n0 + 32*wn + 8*ni + 2*q;
        float bx = 0.f, by = 0.f;
        if (bias) { bx = bias[col]; by = bias[col+1]; }
        #pragma unroll
        for (int mi = 0; mi < MI; mi++) {
            int row_lo = m0 + MI*16*wm + 16*mi + g;
            float v0 = c[mi][ni][0] + bx, v1 = c[mi][ni][1] + by;
            float v2 = c[mi][ni][2] + bx, v3 = c[mi][ni][3] + by;
            if (HALF_OUT) {
                __half* C = (__half*)Cv;
                if (row_lo < M)
                    *(__half2*)(C + (size_t)row_lo*N + col) = __floats2half2_rn(v0, v1);
                if (row_lo + 8 < M)
                    *(__half2*)(C + (size_t)(row_lo+8)*N + col) = __floats2half2_rn(v2, v3);
            } else {
                float* C = (float*)Cv;
                if (row_lo < M)
                    *(float2*)(C + (size_t)row_lo*N + col) = make_float2(v0, v1);
                if (row_lo + 8 < M)
                    *(float2*)(C + (size_t)(row_lo+8)*N + col) = make_float2(v2, v3);
            }
        }
    }
}

#define GEMM_SMEM_MI4 (3*(256*144))     // 110592 -> 2 CTA/SM
#define GEMM_SMEM_MI2 (3*(192*144))     //  82944 -> 2 CTA/SM

// ===========================================================================
// Flash attention (R9 config — best measured). fp16 mma.sync.
// 128 threads = 4 warps, warp tile 32x64, 3-buffer KV ring, one sync/iter,
// register-resident P, __launch_bounds__(128,2).
// SMEM: Q[128] + (K|V)[64] x3 rings, rows 144B = 73728 B.
// ===========================================================================
#define KV0H  9216
#define KVSTG 9216
#define ATT_SMEM ((KV0H + 3*KVSTG) * 2)   // 73728 bytes

__global__ __launch_bounds__(128, 2) void attn_tc(
    const __half* __restrict__ QKV, __half* __restrict__ Og)
{
    extern __shared__ __align__(16) char smraw[];
    const uint32_t sb = s2u(smraw);
    const int tid  = threadIdx.x;
    const int w    = tid >> 5, lane = tid & 31;
    const int g    = lane >> 2, q = lane & 3;
    const int q0   = blockIdx.x * 128;
    const int h    = blockIdx.y;
    const int b    = blockIdx.z;

    const __half* Qg = QKV;
    const __half* Kg = QKV + 1024;
    const __half* Vg = QKV + 2048;

    const uint32_t lmRow = (uint32_t)(lane & 15) * 144 + (uint32_t)(lane >> 4) * 16;
    uint32_t qA[2];
    qA[0] = sb + (uint32_t)(32*w)*144 + lmRow;
    qA[1] = sb + (uint32_t)(32*w + 16)*144 + lmRow;

    // load Q tile: 128 rows x 8 chunks = 1024 chunks, 8/thread  (group 0)
    {
        #pragma unroll
        for (int i = 0; i < 8; i++) {
            int idx = tid + 128*i;
            int row = idx >> 3, lc = idx & 7;
            int s = q0 + row;
            const __half* src = Qg + (size_t)(b*SEQ + (s < SEQ ? s : 0))*NQKV
                                + h*HDIM + lc*8;
            CP16P(sb + row*144 + lc*16, src, (s < SEQ) ? 16 : 0);
        }
        CP_COMMIT();
    }

    const int NKT = (SEQ + 63) / 64;   // 24
    auto load_kv = [&](int kt) {
        const uint32_t Kb = sb + (KV0H + (kt % 3)*KVSTG)*2;
        const uint32_t Vb = Kb + 4608*2;
        #pragma unroll
        for (int i = 0; i < 4; i++) {
            int idx = tid + 128*i;
            int row = idx >> 3, lc = idx & 7;
            int s = kt*64 + row;
            size_t base = (size_t)(b*SEQ + (s < SEQ ? s : 0))*NQKV + h*HDIM + lc*8;
            int ok = (s < SEQ) ? 16 : 0;
            CP16P(Kb + row*144 + lc*16, Kg + base, ok);
            CP16P(Vb + row*144 + lc*16, Vg + base, ok);
        }
    };

    load_kv(0); CP_COMMIT();
    load_kv(1); CP_COMMIT();

    float o[2][8][4];
    float m_lo[2], m_hi[2], l_lo[2], l_hi[2];
    #pragma unroll
    for (int mi = 0; mi < 2; mi++) {
        m_lo[mi] = -1e30f; m_hi[mi] = -1e30f; l_lo[mi] = 0.f; l_hi[mi] = 0.f;
        #pragma unroll
        for (int nt = 0; nt < 8; nt++)
            #pragma unroll
            for (int e = 0; e < 4; e++) o[mi][nt][e] = 0.f;
    }

    for (int kt = 0; kt < NKT; kt++) {
        CP_WAIT(1);
        __syncthreads();

        const uint32_t Kb = sb + (KV0H + (kt % 3)*KVSTG)*2;
        const uint32_t Vb = Kb + 4608*2;

        // ---- S = Q K^T (two m-subtiles share each K fragment) ----
        float s[2][8][4];
        #pragma unroll
        for (int mi = 0; mi < 2; mi++)
            #pragma unroll
            for (int nt = 0; nt < 8; nt++)
                #pragma unroll
                for (int e = 0; e < 4; e++) s[mi][nt][e] = 0.f;

        #pragma unroll
        for (int kd = 0; kd < 4; kd++) {
            uint32_t a[2][4];
            #pragma unroll
            for (int mi = 0; mi < 2; mi++)
                ldsm4(a[mi][0], a[mi][1], a[mi][2], a[mi][3], qA[mi] + kd*32);
            #pragma unroll
            for (int p = 0; p < 4; p++) {
                uint32_t t0, t1, t2, t3;
                ldsm4(t0, t1, t2, t3, Kb + (uint32_t)(16*p)*144 + lmRow + kd*32);
                #pragma unroll
                for (int mi = 0; mi < 2; mi++) {
                    mma16(s[mi][2*p],   a[mi][0], a[mi][1], a[mi][2], a[mi][3], t0, t2);
                    mma16(s[mi][2*p+1], a[mi][0], a[mi][1], a[mi][2], a[mi][3], t1, t3);
                }
            }
        }

        // ---- online softmax per m-subtile ----
        const int jb = kt*64 + 2*q;
        #pragma unroll
        for (int mi = 0; mi < 2; mi++) {
            float mxlo = -1e30f, mxhi = -1e30f;
            #pragma unroll
            for (int nt = 0; nt < 8; nt++) {
                const int j0 = jb + 8*nt;
                s[mi][nt][0] = (j0     < SEQ) ? s[mi][nt][0]*0.125f : -1e30f;
                s[mi][nt][1] = (j0 + 1 < SEQ) ? s[mi][nt][1]*0.125f : -1e30f;
                s[mi][nt][2] = (j0     < SEQ) ? s[mi][nt][2]*0.125f : -1e30f;
                s[mi][nt][3] = (j0 + 1 < SEQ) ? s[mi][nt][3]*0.125f : -1e30f;
                mxlo = fmaxf(mxlo, fmaxf(s[mi][nt][0], s[mi][nt][1]));
                mxhi = fmaxf(mxhi, fmaxf(s[mi][nt][2], s[mi][nt][3]));
            }
            mxlo = fmaxf(mxlo, __shfl_xor_sync(0xffffffffu, mxlo, 1));
            mxlo = fmaxf(mxlo, __shfl_xor_sync(0xffffffffu, mxlo, 2));
            mxhi = fmaxf(mxhi, __shfl_xor_sync(0xffffffffu, mxhi, 1));
            mxhi = fmaxf(mxhi, __shfl_xor_sync(0xffffffffu, mxhi, 2));

            const float mn_lo = fmaxf(m_lo[mi], mxlo);
            const float mn_hi = fmaxf(m_hi[mi], mxhi);
            const float al_lo = __expf(m_lo[mi] - mn_lo);
            const float al_hi = __expf(m_hi[mi] - mn_hi);
            float sl = 0.f, sh = 0.f;
            #pragma unroll
            for (int nt = 0; nt < 8; nt++) {
                s[mi][nt][0] = __expf(s[mi][nt][0] - mn_lo);
                s[mi][nt][1] = __expf(s[mi][nt][1] - mn_lo);
                s[mi][nt][2] = __expf(s[mi][nt][2] - mn_hi);
                s[mi][nt][3] = __expf(s[mi][nt][3] - mn_hi);
                sl += s[mi][nt][0] + s[mi][nt][1];
                sh += s[mi][nt][2] + s[mi][nt][3];
            }
            sl += __shfl_xor_sync(0xffffffffu, sl, 1);
            sl += __shfl_xor_sync(0xffffffffu, sl, 2);
            sh += __shfl_xor_sync(0xffffffffu, sh, 1);
            sh += __shfl_xor_sync(0xffffffffu, sh, 2);
            l_lo[mi] = l_lo[mi] * al_lo + sl;  m_lo[mi] = mn_lo;
            l_hi[mi] = l_hi[mi] * al_hi + sh;  m_hi[mi] = mn_hi;
            #pragma unroll
            for (int nt = 0; nt < 8; nt++) {
                o[mi][nt][0] *= al_lo; o[mi][nt][1] *= al_lo;
                o[mi][nt][2] *= al_hi; o[mi][nt][3] *= al_hi;
            }
        }

        // ---- O += P V : V fragments loaded once, used by both m-subtiles ----
        #pragma unroll
        for (int kj = 0; kj < 4; kj++) {
            uint32_t a[2][4];
            #pragma unroll
            for (int mi = 0; mi < 2; mi++) {
                a[mi][0] = packh2(s[mi][2*kj][0],   s[mi][2*kj][1]);
                a[mi][1] = packh2(s[mi][2*kj][2],   s[mi][2*kj][3]);
                a[mi][2] = packh2(s[mi][2*kj+1][0], s[mi][2*kj+1][1]);
                a[mi][3] = packh2(s[mi][2*kj+1][2], s[mi][2*kj+1][3]);
            }
            const uint32_t vrow = Vb + (uint32_t)(16*kj)*144 + lmRow;
            #pragma unroll
            for (int dt = 0; dt < 4; dt++) {
                uint32_t t0, t1, t2, t3;
                ldsm4t(t0, t1, t2, t3, vrow + dt*32);
                #pragma unroll
                for (int mi = 0; mi < 2; mi++) {
                    mma16(o[mi][2*dt],   a[mi][0], a[mi][1], a[mi][2], a[mi][3], t0, t1);
                    mma16(o[mi][2*dt+1], a[mi][0], a[mi][1], a[mi][2], a[mi][3], t2, t3);
                }
            }
        }

        // prefetch kv(kt+2) into the ring slot freed this iteration
        if (kt + 2 < NKT) load_kv(kt + 2);
        CP_COMMIT();
    }

    // ---- epilogue ----
    #pragma unroll
    for (int mi = 0; mi < 2; mi++) {
        const float il_lo = 1.f / l_lo[mi], il_hi = 1.f / l_hi[mi];
        const int row_lo = q0 + 32*w + 16*mi + g;
        const int row_hi = row_lo + 8;
        #pragma unroll
        for (int nt = 0; nt < 8; nt++) {
            const int d = 8*nt + 2*q;
            if (row_lo < SEQ)
                *(__half2*)(Og + (size_t)(b*SEQ + row_lo)*NSTATE + h*HDIM + d) =
                    __floats2half2_rn(o[mi][nt][0]*il_lo, o[mi][nt][1]*il_lo);
            if (row_hi < SEQ)
                *(__half2*)(Og + (size_t)(b*SEQ + row_hi)*NSTATE + h*HDIM + d) =
                    __floats2half2_rn(o[mi][nt][2]*il_hi, o[mi][nt][3]*il_hi);
        }
    }
}

// ===========================================================================
extern "C" void kernel_launch(void* const* d_in, const int* in_sizes, int n_in,
                              void* d_out, int out_size)
{
    const float* x  = (const float*)d_in[0];
    const float* Wq = (const float*)d_in[1];
    const float* bq = (const float*)d_in[2];
    const float* Wk = (const float*)d_in[3];
    const float* Wv = (const float*)d_in[4];
    const float* bv = (const float*)d_in[5];
    const float* Wo = (const float*)d_in[6];
    const float* bo = (const float*)d_in[7];
    float* out = (float*)d_out;

    __half *xh, *wqkv, *wo, *qkv, *att;
    float* bqkv;
    cudaGetSymbolAddress((void**)&xh,   g_x);
    cudaGetSymbolAddress((void**)&wqkv, g_wqkv);
    cudaGetSymbolAddress((void**)&wo,   g_wo);
    cudaGetSymbolAddress((void**)&qkv,  g_qkv);
    cudaGetSymbolAddress((void**)&att,  g_att);
    cudaGetSymbolAddress((void**)&bqkv, g_bqkv);

    cudaFuncSetAttribute((const void*)gemm_tc<4,true>,
                         cudaFuncAttributeMaxDynamicSharedMemorySize, GEMM_SMEM_MI4);
    cudaFuncSetAttribute((const void*)gemm_tc<2,false>,
                         cudaFuncAttributeMaxDynamicSharedMemorySize, GEMM_SMEM_MI2);
    cudaFuncSetAttribute(attn_tc,
                         cudaFuncAttributeMaxDynamicSharedMemorySize, ATT_SMEM);

    prep_kernel<<<(PREP_CHUNKS + 255)/256, 256>>>(x, Wq, Wk, Wv, Wo, bq, bv);

    // fused QKV projection: [6000,1024] @ [3072,1024]^T -> [6000,3072]
    gemm_tc<4,true><<<dim3(NQKV/128, (TOK+127)/128), 256, GEMM_SMEM_MI4>>>(
        xh, wqkv, bqkv, qkv, TOK, NQKV);

    attn_tc<<<dim3((SEQ+127)/128, NHEAD, BATCH), 128, ATT_SMEM>>>(qkv, att);

    // output projection with 64-row tiles (finer grid -> no 1.27-wave tail)
    gemm_tc<2,false><<<dim3(NSTATE/128, (TOK+63)/64), 256, GEMM_SMEM_MI2>>>(
        att, wo, bo, out, TOK, NSTATE);
}